// round 1
// baseline (speedup 1.0000x reference)
#include <cuda_runtime.h>

#define Bv 8192
#define Nv 256
#define Dv 6
#define Rv 3
#define Hv 32

// 0 = mask stored as int32 (one word per element), 1 = mask stored as 1 byte per element
__device__ int g_mask_is_u8;

__global__ void detect_mask_kernel(const unsigned int* __restrict__ mw) {
    __shared__ int any_gt1;
    if (threadIdx.x == 0) any_gt1 = 0;
    __syncthreads();
    int found = 0;
    // 4096 words is within bounds for both interpretations:
    //   int32 mask: B*N = 2,097,152 words; uint8 mask: B*N/4 = 524,288 words
    for (int i = threadIdx.x; i < 4096; i += blockDim.x) {
        if (mw[i] > 1u) found = 1;
    }
    if (found) any_gt1 = 1;  // benign race: all writers store 1
    __syncthreads();
    if (threadIdx.x == 0) g_mask_is_u8 = any_gt1;
}

__global__ __launch_bounds__(Nv, 1)
void hmf_encoder_kernel(const float* __restrict__ states,
                        const int*   __restrict__ roles,
                        const void*  __restrict__ maskp,
                        const float* __restrict__ trust,
                        const float* __restrict__ W1,
                        const float* __restrict__ b1,
                        const float* __restrict__ W2,
                        const float* __restrict__ b2,
                        float* __restrict__ out)
{
    __shared__ float sW1[Rv * Dv * Hv];   // 576
    __shared__ float sb1[Rv * Hv];        // 96
    __shared__ float sW2[Rv * Hv];        // 96
    __shared__ float sb2[Rv];             // 3
    __shared__ float sx[Nv * Dv];         // 1536
    __shared__ float s_e[Nv];
    __shared__ float s_ew[Nv];
    __shared__ int   s_role[Nv];
    __shared__ float warp_max[8][3];
    __shared__ float sm[Rv];

    const int b   = blockIdx.x;
    const int tid = threadIdx.x;
    const int lane = tid & 31;
    const int wid  = tid >> 5;
    const size_t base = (size_t)b * Nv;

    // ---- stage params + state tile into SMEM (coalesced) ----
    #pragma unroll
    for (int i = tid; i < Rv * Dv * Hv; i += Nv) sW1[i] = W1[i];
    if (tid < Rv * Hv) { sb1[tid] = b1[tid]; sW2[tid] = W2[tid]; }
    if (tid < Rv) sb2[tid] = b2[tid];
    const float* xb = states + base * Dv;
    #pragma unroll
    for (int i = tid; i < Nv * Dv; i += Nv) sx[i] = xb[i];
    __syncthreads();

    // ---- per-neighbor loads ----
    const int role = roles[base + tid];
    int mk;
    if (g_mask_is_u8) mk = ((const unsigned char*)maskp)[base + tid];
    else              mk = ((const int*)maskp)[base + tid];
    const bool act = (mk != 0);
    const float twv = act ? trust[base + tid] : 0.0f;

    float xr[Dv];
    #pragma unroll
    for (int d = 0; d < Dv; d++) xr[d] = sx[tid * Dv + d];

    // ---- tiny MLP: score for this neighbor's own role only ----
    float score;
    {
        const float* w1  = sW1 + role * Dv * Hv;
        const float* bb1 = sb1 + role * Hv;
        const float* w2  = sW2 + role * Hv;
        float acc = sb2[role];
        #pragma unroll
        for (int h = 0; h < Hv; h++) {
            float hv = bb1[h];
            #pragma unroll
            for (int d = 0; d < Dv; d++) hv = fmaf(xr[d], w1[d * Hv + h], hv);
            hv = fmaxf(hv, 0.0f);
            acc = fmaf(hv, w2[h], acc);
        }
        score = act ? acc : 0.0f;   // == scores * role_mask at this (n, role)
    }

    // ---- per-role max over masked scores (inactive / other-role entries = 0) ----
    float vm0 = 0.0f, vm1 = 0.0f, vm2 = 0.0f;
    if (act) {
        if (role == 0)      vm0 = score;
        else if (role == 1) vm1 = score;
        else                vm2 = score;
    }
    #pragma unroll
    for (int o = 16; o; o >>= 1) {
        vm0 = fmaxf(vm0, __shfl_xor_sync(0xffffffffu, vm0, o));
        vm1 = fmaxf(vm1, __shfl_xor_sync(0xffffffffu, vm1, o));
        vm2 = fmaxf(vm2, __shfl_xor_sync(0xffffffffu, vm2, o));
    }
    if (lane == 0) {
        warp_max[wid][0] = vm0;
        warp_max[wid][1] = vm1;
        warp_max[wid][2] = vm2;
    }
    __syncthreads();
    if (tid < Rv) {
        float m = warp_max[0][tid];
        #pragma unroll
        for (int w = 1; w < 8; w++) m = fmaxf(m, warp_max[w][tid]);
        sm[tid] = m;
    }
    __syncthreads();

    // ---- exponentials ----
    const float e = act ? __expf(score - sm[role]) : 0.0f;
    s_e[tid]  = e;
    s_ew[tid] = e * twv;
    s_role[tid] = role;
    __syncthreads();

    // ---- warps 0..2: accumulate per-role den / wsum / num[6], then write out ----
    if (wid < Rv) {
        const int r = wid;
        float den = 0.0f, ws = 0.0f;
        float num[Dv] = {0.f, 0.f, 0.f, 0.f, 0.f, 0.f};
        #pragma unroll
        for (int i = 0; i < Nv / 32; i++) {
            const int n = lane + i * 32;
            if (s_role[n] == r) {
                const float ev  = s_e[n];
                const float ewv = s_ew[n];
                den += ev;
                ws  += ewv;
                #pragma unroll
                for (int d = 0; d < Dv; d++)
                    num[d] = fmaf(ewv, sx[n * Dv + d], num[d]);
            }
        }
        #pragma unroll
        for (int o = 16; o; o >>= 1) {
            den += __shfl_xor_sync(0xffffffffu, den, o);
            ws  += __shfl_xor_sync(0xffffffffu, ws,  o);
            #pragma unroll
            for (int d = 0; d < Dv; d++)
                num[d] += __shfl_xor_sync(0xffffffffu, num[d], o);
        }
        if (lane < Dv) {
            const float inv = 1.0f / (den + 1e-8f);
            const float wsv = fmaxf(ws * inv, 1e-8f);
            out[(size_t)b * (Rv * Dv) + r * Dv + lane] = num[lane] * inv / wsv;
        }
    }
}

extern "C" void kernel_launch(void* const* d_in, const int* in_sizes, int n_in,
                              void* d_out, int out_size) {
    const float* states = (const float*)d_in[0];
    const int*   roles  = (const int*)d_in[1];
    const void*  maskp  = d_in[2];
    const float* trust  = (const float*)d_in[3];
    const float* W1     = (const float*)d_in[4];
    const float* b1     = (const float*)d_in[5];
    const float* W2     = (const float*)d_in[6];
    const float* b2     = (const float*)d_in[7];
    float* out = (float*)d_out;

    detect_mask_kernel<<<1, 256>>>((const unsigned int*)maskp);
    hmf_encoder_kernel<<<Bv, Nv>>>(states, roles, maskp, trust, W1, b1, W2, b2, out);
}

// round 3
// speedup vs baseline: 2.1278x; 2.1278x over previous
#include <cuda_runtime.h>

#define Bv 8192
#define Nv 256
#define Dv 6
#define Rv 3
#define Hv 32

// packed weights: [role][h][8] = {W1 d0..d5, b1[h], W2[h]}, role stride 264 words
// (264 mod 32 == 8 so the three role segments live in disjoint SMEM banks;
//  264 words = 66*16B so per-role segments stay 16B-aligned)
#define RSTRIDE 264
__device__ float g_pack[Rv * RSTRIDE];
__device__ float g_b2[Rv];
__device__ int   g_mask_is_u8;   // 0 = int32 mask, 1 = uint8 mask

__global__ void prep_kernel(const float* __restrict__ W1,
                            const float* __restrict__ b1,
                            const float* __restrict__ W2,
                            const float* __restrict__ b2,
                            const unsigned int* __restrict__ mw) {
    __shared__ int any_gt1;
    const int t = threadIdx.x;
    if (t == 0) any_gt1 = 0;
    __syncthreads();

    // mask dtype detection: 4096 words is in-bounds under both layouts
    int found = 0;
    for (int i = t; i < 4096; i += blockDim.x)
        if (mw[i] > 1u) found = 1;
    if (found) any_gt1 = 1;
    __syncthreads();
    if (t == 0) g_mask_is_u8 = any_gt1;

    // weight repack: one (role, h) pair per thread
    if (t < Rv * Hv) {
        const int r = t / Hv, h = t % Hv;
        float* dst = g_pack + r * RSTRIDE + h * 8;
        #pragma unroll
        for (int d = 0; d < Dv; d++) dst[d] = W1[r * Dv * Hv + d * Hv + h];
        dst[6] = b1[r * Hv + h];
        dst[7] = W2[r * Hv + h];
    }
    if (t < Rv) g_b2[t] = b2[t];
}

__global__ __launch_bounds__(Nv, 3)
void hmf_encoder_kernel(const float* __restrict__ states,
                        const int*   __restrict__ roles,
                        const void*  __restrict__ maskp,
                        const float* __restrict__ trust,
                        float* __restrict__ out)
{
    __shared__ __align__(16) float sPack[Rv * RSTRIDE];   // 3168 B
    __shared__ float sb2[Rv];
    __shared__ __align__(16) float sx[Nv * Dv];           // 6 KB state tile
    __shared__ float s_e[Nv];
    __shared__ float s_ew[Nv];
    __shared__ int   s_role[Nv];
    __shared__ float warp_max[8][3];
    __shared__ float sm[Rv];

    const int b    = blockIdx.x;
    const int tid  = threadIdx.x;
    const int lane = tid & 31;
    const int wid  = tid >> 5;
    const size_t base = (size_t)b * Nv;

    // ---- stage packed params + state tile (coalesced, vectorized) ----
    #pragma unroll
    for (int i = tid; i < Rv * RSTRIDE; i += Nv) sPack[i] = g_pack[i];
    if (tid < Rv) sb2[tid] = g_b2[tid];
    {
        const float4* xb4 = (const float4*)(states + base * Dv);
        float4* sx4 = (float4*)sx;
        #pragma unroll
        for (int i = tid; i < (Nv * Dv) / 4; i += Nv) sx4[i] = xb4[i];
    }
    __syncthreads();

    // ---- per-neighbor loads ----
    const int role = roles[base + tid];
    int mk;
    if (g_mask_is_u8) mk = ((const unsigned char*)maskp)[base + tid];
    else              mk = ((const int*)maskp)[base + tid];
    const bool act = (mk != 0);
    const float twv = act ? trust[base + tid] : 0.0f;

    const float2* xp = (const float2*)(sx + tid * Dv);   // 8B-aligned (tid*24, sx 16B-aligned)
    const float2 p0 = xp[0], p1 = xp[1], p2 = xp[2];

    // ---- tiny MLP for this neighbor's own role ----
    float score;
    {
        const float* wr = sPack + role * RSTRIDE;
        float acc0 = 0.0f, acc1 = 0.0f;
        #pragma unroll
        for (int h = 0; h < Hv; h += 2) {
            const float4 a0 = *(const float4*)(wr + h * 8);
            const float4 c0 = *(const float4*)(wr + h * 8 + 4);
            const float4 a1 = *(const float4*)(wr + h * 8 + 8);
            const float4 c1 = *(const float4*)(wr + h * 8 + 12);
            float hv0 = fmaf(p0.x, a0.x, fmaf(p0.y, a0.y,
                        fmaf(p1.x, a0.z, fmaf(p1.y, a0.w,
                        fmaf(p2.x, c0.x, fmaf(p2.y, c0.y, c0.z))))));
            float hv1 = fmaf(p0.x, a1.x, fmaf(p0.y, a1.y,
                        fmaf(p1.x, a1.z, fmaf(p1.y, a1.w,
                        fmaf(p2.x, c1.x, fmaf(p2.y, c1.y, c1.z))))));
            acc0 = fmaf(fmaxf(hv0, 0.0f), c0.w, acc0);
            acc1 = fmaf(fmaxf(hv1, 0.0f), c1.w, acc1);
        }
        const float acc = acc0 + acc1 + sb2[role];
        score = act ? acc : 0.0f;   // == scores * role_mask at (n, own role)
    }

    // ---- per-role max over masked scores (zeros included, per reference) ----
    float vm0 = 0.0f, vm1 = 0.0f, vm2 = 0.0f;
    if (act) {
        if (role == 0)      vm0 = score;
        else if (role == 1) vm1 = score;
        else                vm2 = score;
    }
    #pragma unroll
    for (int o = 16; o; o >>= 1) {
        vm0 = fmaxf(vm0, __shfl_xor_sync(0xffffffffu, vm0, o));
        vm1 = fmaxf(vm1, __shfl_xor_sync(0xffffffffu, vm1, o));
        vm2 = fmaxf(vm2, __shfl_xor_sync(0xffffffffu, vm2, o));
    }
    if (lane == 0) {
        warp_max[wid][0] = vm0;
        warp_max[wid][1] = vm1;
        warp_max[wid][2] = vm2;
    }
    __syncthreads();
    if (tid < Rv) {
        float m = warp_max[0][tid];
        #pragma unroll
        for (int w = 1; w < 8; w++) m = fmaxf(m, warp_max[w][tid]);
        sm[tid] = m;
    }
    __syncthreads();

    // ---- exponentials ----
    const float e = act ? __expf(score - sm[role]) : 0.0f;
    s_e[tid]  = e;
    s_ew[tid] = e * twv;
    s_role[tid] = role;
    __syncthreads();

    // ---- warps 0..2: per-role den / wsum / num[6] reductions, then write ----
    if (wid < Rv) {
        const int r = wid;
        float den = 0.0f, ws = 0.0f;
        float num[Dv] = {0.f, 0.f, 0.f, 0.f, 0.f, 0.f};
        #pragma unroll
        for (int i = 0; i < Nv / 32; i++) {
            const int n = lane + i * 32;
            if (s_role[n] == r) {
                const float ev  = s_e[n];
                const float ewv = s_ew[n];
                den += ev;
                ws  += ewv;
                #pragma unroll
                for (int d = 0; d < Dv; d++)
                    num[d] = fmaf(ewv, sx[n * Dv + d], num[d]);
            }
        }
        #pragma unroll
        for (int o = 16; o; o >>= 1) {
            den += __shfl_xor_sync(0xffffffffu, den, o);
            ws  += __shfl_xor_sync(0xffffffffu, ws,  o);
            #pragma unroll
            for (int d = 0; d < Dv; d++)
                num[d] += __shfl_xor_sync(0xffffffffu, num[d], o);
        }
        if (lane < Dv) {
            const float inv = 1.0f / (den + 1e-8f);
            const float wsv = fmaxf(ws * inv, 1e-8f);
            out[(size_t)b * (Rv * Dv) + r * Dv + lane] = num[lane] * inv / wsv;
        }
    }
}

extern "C" void kernel_launch(void* const* d_in, const int* in_sizes, int n_in,
                              void* d_out, int out_size) {
    const float* states = (const float*)d_in[0];
    const int*   roles  = (const int*)d_in[1];
    const void*  maskp  = d_in[2];
    const float* trust  = (const float*)d_in[3];
    const float* W1     = (const float*)d_in[4];
    const float* b1     = (const float*)d_in[5];
    const float* W2     = (const float*)d_in[6];
    const float* b2     = (const float*)d_in[7];
    float* out = (float*)d_out;

    prep_kernel<<<1, 256>>>(W1, b1, W2, b2, (const unsigned int*)maskp);
    hmf_encoder_kernel<<<Bv, Nv>>>(states, roles, maskp, trust, out);
}